// round 4
// baseline (speedup 1.0000x reference)
#include <cuda_runtime.h>
#include <cuda_bf16.h>

#define N_NODES 131072
#define P_NODES 4096
#define B_GR    32
#define E_EDGES 2097152
#define IN_DIM  64
#define HID     128
#define OUT_DIM 16
#define CAP     64          // max in-degree slots (Poisson(16): P(>=64) ~ 3e-22/node)
#define EPSV    1e-5f
#define SLOPE   0.01f

// ---------------- scratch (device globals: no allocations allowed) ----------
__device__ int   g_deg_src[N_NODES];
__device__ int   g_deg_dst[N_NODES];
__device__ int   g_cursor[N_NODES];
__device__ float g_rs_src[N_NODES];
__device__ float g_rs_dst[N_NODES];
__device__ int   g_csr_src[(size_t)N_NODES * CAP];
__device__ float g_csr_w[(size_t)N_NODES * CAP];
__device__ float g_h1pre[(size_t)N_NODES * HID];
__device__ float g_h1[(size_t)N_NODES * HID];
__device__ float g_h2pre[(size_t)N_NODES * HID];
__device__ float g_stats1[2 * HID];     // [sum(128) | sumsq(128)]
__device__ float g_stats2[2 * HID];
__device__ float g_r[B_GR * 2 * HID];   // per-graph readout sums [32][256]

// ---------------- kernels ---------------------------------------------------

__global__ void k_zero() {
    int i = blockIdx.x * blockDim.x + threadIdx.x;
    if (i < N_NODES) { g_deg_src[i] = 0; g_deg_dst[i] = 0; g_cursor[i] = 0; }
    if (i < 2 * HID) { g_stats1[i] = 0.f; g_stats2[i] = 0.f; }
    if (i < B_GR * 2 * HID) { g_r[i] = 0.f; }
}

__global__ void k_deg(const int* __restrict__ src, const int* __restrict__ dst) {
    int e = blockIdx.x * blockDim.x + threadIdx.x;
    if (e < E_EDGES) {
        atomicAdd(&g_deg_src[src[e]], 1);
        atomicAdd(&g_deg_dst[dst[e]], 1);
    }
}

__global__ void k_rs() {
    int v = blockIdx.x * blockDim.x + threadIdx.x;
    if (v < N_NODES) {
        g_rs_src[v] = rsqrtf((float)max(g_deg_src[v], 1));
        g_rs_dst[v] = rsqrtf((float)max(g_deg_dst[v], 1));
    }
}

__global__ void k_fill(const int* __restrict__ src, const int* __restrict__ dst,
                       const float* __restrict__ ew) {
    int e = blockIdx.x * blockDim.x + threadIdx.x;
    if (e < E_EDGES) {
        int d = dst[e];
        int s = src[e];
        int pos = atomicAdd(&g_cursor[d], 1);
        if (pos < CAP) {
            g_csr_src[(size_t)d * CAP + pos] = s;
            g_csr_w[(size_t)d * CAP + pos]   = ew[e] * g_rs_src[s];  // fold D_out^-1/2
        }
    }
}

// Layer 1: gather(64) + matvec 64->128 fused; warp per node, W1 in smem.
__global__ void k_layer1(const float* __restrict__ x, const float* __restrict__ W1) {
    __shared__ float sW[IN_DIM * HID];        // 32 KB
    __shared__ float sAcc[8][IN_DIM];
    int tid = threadIdx.x;
    for (int i = tid; i < IN_DIM * HID; i += 256) sW[i] = W1[i];
    __syncthreads();

    int w = tid >> 5, lane = tid & 31;
    int v = blockIdx.x * 8 + w;

    float a0 = 0.f, a1 = 0.f;
    int deg = min(g_deg_dst[v], CAP);
    const int*   cs = &g_csr_src[(size_t)v * CAP];
    const float* cw = &g_csr_w[(size_t)v * CAP];

    for (int base = 0; base < deg; base += 32) {
        int n = min(32, deg - base);
        int s = 0; float wt = 0.f;
        if (lane < n) { s = cs[base + lane]; wt = cw[base + lane]; }
        for (int i = 0; i < n; i++) {
            int   ss = __shfl_sync(0xffffffffu, s, i);
            float ww = __shfl_sync(0xffffffffu, wt, i);
            float2 val = ((const float2*)&x[(size_t)ss * IN_DIM])[lane];
            a0 += ww * val.x;
            a1 += ww * val.y;
        }
    }
    float rd = g_rs_dst[v];
    sAcc[w][2 * lane]     = a0 * rd;
    sAcc[w][2 * lane + 1] = a1 * rd;
    __syncwarp();

    float o0 = 0.f, o1 = 0.f, o2 = 0.f, o3 = 0.f;
    #pragma unroll 8
    for (int k = 0; k < IN_DIM; k++) {
        float av = sAcc[w][k];
        const float* wr = &sW[k * HID];
        o0 += av * wr[lane];
        o1 += av * wr[lane + 32];
        o2 += av * wr[lane + 64];
        o3 += av * wr[lane + 96];
    }
    float* out = &g_h1pre[(size_t)v * HID];
    out[lane] = o0; out[lane + 32] = o1; out[lane + 64] = o2; out[lane + 96] = o3;
}

// Layer 2: gather(128) + matvec 128->128 fused; dynamic smem for W2 (64KB) + staging.
__global__ void k_layer2(const float* __restrict__ W2) {
    extern __shared__ float sm[];
    float* sW   = sm;                 // 128*128 floats
    float* sAcc = sm + HID * HID;     // 8*128 floats
    int tid = threadIdx.x;
    for (int i = tid; i < HID * HID; i += 256) sW[i] = W2[i];
    __syncthreads();

    int w = tid >> 5, lane = tid & 31;
    int v = blockIdx.x * 8 + w;

    float a0 = 0.f, a1 = 0.f, a2 = 0.f, a3 = 0.f;
    int deg = min(g_deg_dst[v], CAP);
    const int*   cs = &g_csr_src[(size_t)v * CAP];
    const float* cw = &g_csr_w[(size_t)v * CAP];

    for (int base = 0; base < deg; base += 32) {
        int n = min(32, deg - base);
        int s = 0; float wt = 0.f;
        if (lane < n) { s = cs[base + lane]; wt = cw[base + lane]; }
        for (int i = 0; i < n; i++) {
            int   ss = __shfl_sync(0xffffffffu, s, i);
            float ww = __shfl_sync(0xffffffffu, wt, i);
            float4 val = ((const float4*)&g_h1[(size_t)ss * HID])[lane];
            a0 += ww * val.x;
            a1 += ww * val.y;
            a2 += ww * val.z;
            a3 += ww * val.w;
        }
    }
    float rd = g_rs_dst[v];
    float* sa = &sAcc[w * HID];
    sa[4 * lane]     = a0 * rd;
    sa[4 * lane + 1] = a1 * rd;
    sa[4 * lane + 2] = a2 * rd;
    sa[4 * lane + 3] = a3 * rd;
    __syncwarp();

    float o0 = 0.f, o1 = 0.f, o2 = 0.f, o3 = 0.f;
    #pragma unroll 8
    for (int k = 0; k < HID; k++) {
        float av = sa[k];
        const float* wr = &sW[k * HID];
        o0 += av * wr[lane];
        o1 += av * wr[lane + 32];
        o2 += av * wr[lane + 64];
        o3 += av * wr[lane + 96];
    }
    float* out = &g_h2pre[(size_t)v * HID];
    out[lane] = o0; out[lane + 32] = o1; out[lane + 64] = o2; out[lane + 96] = o3;
}

// Feature-wise sum & sumsq over all nodes. grid=512 blocks x 128 threads.
// layer selects device-global source/dest (cannot pass __device__ symbols from host!).
__global__ void k_stats(int layer) {
    int j = threadIdx.x;
    const float* h   = (layer == 1) ? g_h1pre : g_h2pre;
    float* stats     = (layer == 1) ? g_stats1 : g_stats2;
    const float* base = &h[(size_t)blockIdx.x * 256 * HID];
    float s = 0.f, ss = 0.f;
    for (int r = 0; r < 256; r++) {
        float v = base[r * HID + j];
        s += v;
        ss += v * v;
    }
    atomicAdd(&stats[j], s);
    atomicAdd(&stats[HID + j], ss);
}

// GraphNorm + leaky relu + per-graph readout partial sums.
// layer 1: reads g_h1pre, writes g_h1, accumulates into r columns [0,HID).
// layer 2: reads g_h2pre, no write, accumulates into r columns [HID,2*HID).
__global__ void k_norm(int layer,
                       const float* __restrict__ gamma, const float* __restrict__ beta,
                       const float* __restrict__ alpha) {
    int j = threadIdx.x;
    int b = blockIdx.x;
    const float* stats = (layer == 1) ? g_stats1 : g_stats2;
    const float* hpre  = (layer == 1) ? g_h1pre : g_h2pre;
    int rcol  = (layer == 1) ? 0 : HID;
    int writeH = (layer == 1) ? 1 : 0;

    const float invN = 1.0f / (float)N_NODES;
    float mu  = stats[j] * invN;
    float ex2 = stats[HID + j] * invN;
    float al  = alpha[j];
    // var = E[x^2] - 2*al*mu*E[x] + al^2*mu^2
    float var = ex2 + mu * mu * (al * al - 2.f * al);
    float istd = rsqrtf(var + EPSV);
    float ga = gamma[j] * istd;
    float be = beta[j];
    float amu = al * mu;

    int g = (b * 256) / P_NODES;
    const float* in = &hpre[(size_t)b * 256 * HID];
    float* out = &g_h1[(size_t)b * 256 * HID];
    float rsum = 0.f;
    for (int r = 0; r < 256; r++) {
        float v = in[r * HID + j];
        float c = (v - amu) * ga + be;
        float y = c > 0.f ? c : SLOPE * c;
        if (writeH) out[r * HID + j] = y;
        rsum += y;
    }
    atomicAdd(&g_r[g * (2 * HID) + rcol + j], rsum);
}

// Final tiny GEMM: out[b][o] = (1/P) * sum_k r[b][k] * Wc[o][k]
__global__ void k_final(const float* __restrict__ Wc, float* __restrict__ out) {
    int t = threadIdx.x;      // 512 threads
    int b = t >> 4, o = t & 15;
    const float* rb = &g_r[b * 2 * HID];
    const float* wr = &Wc[o * 2 * HID];
    float s = 0.f;
    #pragma unroll 8
    for (int k = 0; k < 2 * HID; k++) s += rb[k] * wr[k];
    out[b * OUT_DIM + o] = s * (1.0f / (float)P_NODES);
}

// ---------------- launch -----------------------------------------------------

extern "C" void kernel_launch(void* const* d_in, const int* in_sizes, int n_in,
                              void* d_out, int out_size) {
    const float* features = (const float*)d_in[0];
    const float* ew       = (const float*)d_in[1];
    const int*   src      = (const int*)d_in[2];
    const int*   dst      = (const int*)d_in[3];
    const float* W1       = (const float*)d_in[4];
    const float* W2       = (const float*)d_in[5];
    const float* Wc       = (const float*)d_in[6];
    const float* gamma1   = (const float*)d_in[7];
    const float* beta1    = (const float*)d_in[8];
    const float* alpha1   = (const float*)d_in[9];
    const float* gamma2   = (const float*)d_in[10];
    const float* beta2    = (const float*)d_in[11];
    const float* alpha2   = (const float*)d_in[12];
    float* out = (float*)d_out;

    const int smem2 = (HID * HID + 8 * HID) * (int)sizeof(float);  // 68 KB
    cudaFuncSetAttribute(k_layer2, cudaFuncAttributeMaxDynamicSharedMemorySize, smem2);

    // 0) zero scratch
    k_zero<<<N_NODES / 256, 256>>>();
    // 1) degree histograms
    k_deg<<<E_EDGES / 256, 256>>>(src, dst);
    // 2) rsqrt degrees
    k_rs<<<N_NODES / 256, 256>>>();
    // 3) padded CSR fill (weight pre-scaled by rsqrt(deg_src))
    k_fill<<<E_EDGES / 256, 256>>>(src, dst, ew);
    // 4) layer 1: gather + matvec
    k_layer1<<<N_NODES / 8, 256>>>(features, W1);
    // 5) norm 1 stats + apply (writes g_h1, accumulates r1)
    k_stats<<<512, 128>>>(1);
    k_norm<<<512, 128>>>(1, gamma1, beta1, alpha1);
    // 6) layer 2: gather + matvec
    k_layer2<<<N_NODES / 8, 256, smem2>>>(W2);
    // 7) norm 2 stats + apply (readout only, no h2 materialization)
    k_stats<<<512, 128>>>(2);
    k_norm<<<512, 128>>>(2, gamma2, beta2, alpha2);
    // 8) readout GEMM
    k_final<<<1, 512>>>(Wc, out);
}

// round 5
// speedup vs baseline: 1.2025x; 1.2025x over previous
#include <cuda_runtime.h>
#include <cuda_fp16.h>

#define N_NODES 131072
#define P_NODES 4096
#define B_GR    32
#define E_EDGES 2097152
#define IN_DIM  64
#define HID     128
#define OUT_DIM 16
#define CAP     64          // max in-degree slots (Poisson(16): overflow P ~ 1e-21)
#define EPSV    1e-5f
#define SLOPE   0.01f

// ---------------- scratch (device globals; no allocations allowed) ----------
__device__ int    g_deg_src[N_NODES];
__device__ int    g_cursor[N_NODES];          // becomes dst degree after build
__device__ float  g_rs_src[N_NODES];
__device__ int    g_csr_src[(size_t)N_NODES * CAP];
__device__ float  g_csr_w[(size_t)N_NODES * CAP];   // raw edge weight (rs_src folded at gather)
__device__ float  g_h1pre[(size_t)N_NODES * HID];
__device__ __half g_h1h[(size_t)N_NODES * HID];     // normalized h1 in fp16 (gather source)
__device__ float  g_h2pre[(size_t)N_NODES * HID];
__device__ float  g_stats1[2 * HID];
__device__ float  g_stats2[2 * HID];
__device__ float  g_r[B_GR * 2 * HID];

// ---------------- setup kernels ---------------------------------------------

__global__ void k_zero() {
    int i = blockIdx.x * blockDim.x + threadIdx.x;
    if (i < N_NODES) { g_deg_src[i] = 0; g_cursor[i] = 0; }
    if (i < 2 * HID) { g_stats1[i] = 0.f; g_stats2[i] = 0.f; }
    if (i < B_GR * 2 * HID) { g_r[i] = 0.f; }
}

// Single pass: dst-CSR fill (cursor atomic doubles as dst-degree histogram)
// plus src-degree histogram.
__global__ void k_build(const int* __restrict__ src, const int* __restrict__ dst,
                        const float* __restrict__ ew) {
    int e = blockIdx.x * blockDim.x + threadIdx.x;
    if (e < E_EDGES) {
        int d = dst[e];
        int s = src[e];
        int pos = atomicAdd(&g_cursor[d], 1);
        atomicAdd(&g_deg_src[s], 1);
        if (pos < CAP) {
            g_csr_src[(size_t)d * CAP + pos] = s;
            g_csr_w[(size_t)d * CAP + pos]   = ew[e];
        }
    }
}

__global__ void k_rs() {
    int v = blockIdx.x * blockDim.x + threadIdx.x;
    if (v < N_NODES) g_rs_src[v] = rsqrtf((float)max(g_deg_src[v], 1));
}

// ---------------- layer 1: gather(fp32,64) + matvec 64->128 -----------------
// 512 threads = 16 warps; warp per node; W1 (32KB) shared by whole block.
__global__ __launch_bounds__(512) void k_layer1(const float* __restrict__ x,
                                                const float* __restrict__ W1) {
    __shared__ float sW[IN_DIM * HID];        // 32 KB
    __shared__ float sAcc[16][IN_DIM];        // 4 KB
    int tid = threadIdx.x;
    for (int i = tid; i < IN_DIM * HID; i += 512) sW[i] = W1[i];
    __syncthreads();

    int w = tid >> 5, lane = tid & 31;
    int v = blockIdx.x * 16 + w;

    int degf = g_cursor[v];
    int deg  = min(degf, CAP);
    const int*   cs = &g_csr_src[(size_t)v * CAP];
    const float* cw = &g_csr_w[(size_t)v * CAP];

    float a0 = 0.f, a1 = 0.f;
    for (int base = 0; base < deg; base += 32) {
        int n = min(32, deg - base);
        int s = 0; float wt = 0.f;
        if (lane < n) {
            s  = cs[base + lane];
            wt = cw[base + lane] * g_rs_src[s];
        }
        // 4 edges per iteration: 4 independent loads in flight (MLP=4).
        for (int i = 0; i < n; i += 4) {
            int j1 = min(i + 1, 31), j2 = min(i + 2, 31), j3 = min(i + 3, 31);
            int   s0 = __shfl_sync(0xffffffffu, s,  i);
            int   s1 = __shfl_sync(0xffffffffu, s,  j1);
            int   s2 = __shfl_sync(0xffffffffu, s,  j2);
            int   s3 = __shfl_sync(0xffffffffu, s,  j3);
            float w0 = __shfl_sync(0xffffffffu, wt, i);
            float w1 = (i + 1 < n) ? __shfl_sync(0xffffffffu, wt, j1) : 0.f;
            float w2 = (i + 2 < n) ? __shfl_sync(0xffffffffu, wt, j2) : 0.f;
            float w3 = (i + 3 < n) ? __shfl_sync(0xffffffffu, wt, j3) : 0.f;
            float2 v0 = ((const float2*)&x[(size_t)s0 * IN_DIM])[lane];
            float2 v1 = ((const float2*)&x[(size_t)s1 * IN_DIM])[lane];
            float2 v2 = ((const float2*)&x[(size_t)s2 * IN_DIM])[lane];
            float2 v3 = ((const float2*)&x[(size_t)s3 * IN_DIM])[lane];
            a0 += w0 * v0.x + w1 * v1.x + w2 * v2.x + w3 * v3.x;
            a1 += w0 * v0.y + w1 * v1.y + w2 * v2.y + w3 * v3.y;
        }
    }
    float rd = rsqrtf((float)max(degf, 1));
    sAcc[w][2 * lane]     = a0 * rd;
    sAcc[w][2 * lane + 1] = a1 * rd;
    __syncwarp();

    float o0 = 0.f, o1 = 0.f, o2 = 0.f, o3 = 0.f;
    #pragma unroll 8
    for (int k = 0; k < IN_DIM; k++) {
        float av = sAcc[w][k];
        const float* wr = &sW[k * HID];
        o0 += av * wr[lane];
        o1 += av * wr[lane + 32];
        o2 += av * wr[lane + 64];
        o3 += av * wr[lane + 96];
    }
    float* out = &g_h1pre[(size_t)v * HID];
    out[lane] = o0; out[lane + 32] = o1; out[lane + 64] = o2; out[lane + 96] = o3;
}

// ---------------- layer 2: gather(fp16,128) + matvec 128->128 ---------------
// 512 threads; dynamic smem: W2 fp32 (64KB) + staging (8KB) = 72KB -> 3 blocks/SM.
__global__ __launch_bounds__(512) void k_layer2(const float* __restrict__ W2) {
    extern __shared__ float sm[];
    float* sW   = sm;                  // 128*128
    float* sAcc = sm + HID * HID;      // 16*128
    int tid = threadIdx.x;
    for (int i = tid; i < HID * HID; i += 512) sW[i] = W2[i];
    __syncthreads();

    int w = tid >> 5, lane = tid & 31;
    int v = blockIdx.x * 16 + w;

    int degf = g_cursor[v];
    int deg  = min(degf, CAP);
    const int*   cs = &g_csr_src[(size_t)v * CAP];
    const float* cw = &g_csr_w[(size_t)v * CAP];

    float a0 = 0.f, a1 = 0.f, a2 = 0.f, a3 = 0.f;
    for (int base = 0; base < deg; base += 32) {
        int n = min(32, deg - base);
        int s = 0; float wt = 0.f;
        if (lane < n) {
            s  = cs[base + lane];
            wt = cw[base + lane] * g_rs_src[s];
        }
        for (int i = 0; i < n; i += 4) {
            int j1 = min(i + 1, 31), j2 = min(i + 2, 31), j3 = min(i + 3, 31);
            int   s0 = __shfl_sync(0xffffffffu, s,  i);
            int   s1 = __shfl_sync(0xffffffffu, s,  j1);
            int   s2 = __shfl_sync(0xffffffffu, s,  j2);
            int   s3 = __shfl_sync(0xffffffffu, s,  j3);
            float w0 = __shfl_sync(0xffffffffu, wt, i);
            float w1 = (i + 1 < n) ? __shfl_sync(0xffffffffu, wt, j1) : 0.f;
            float w2 = (i + 2 < n) ? __shfl_sync(0xffffffffu, wt, j2) : 0.f;
            float w3 = (i + 3 < n) ? __shfl_sync(0xffffffffu, wt, j3) : 0.f;
            // each lane: 4 halves (features 4*lane .. 4*lane+3) = 8B
            uint2 u0 = ((const uint2*)&g_h1h[(size_t)s0 * HID])[lane];
            uint2 u1 = ((const uint2*)&g_h1h[(size_t)s1 * HID])[lane];
            uint2 u2 = ((const uint2*)&g_h1h[(size_t)s2 * HID])[lane];
            uint2 u3 = ((const uint2*)&g_h1h[(size_t)s3 * HID])[lane];
            float2 p, q;
            p = __half22float2(*(const __half2*)&u0.x); q = __half22float2(*(const __half2*)&u0.y);
            a0 += w0 * p.x; a1 += w0 * p.y; a2 += w0 * q.x; a3 += w0 * q.y;
            p = __half22float2(*(const __half2*)&u1.x); q = __half22float2(*(const __half2*)&u1.y);
            a0 += w1 * p.x; a1 += w1 * p.y; a2 += w1 * q.x; a3 += w1 * q.y;
            p = __half22float2(*(const __half2*)&u2.x); q = __half22float2(*(const __half2*)&u2.y);
            a0 += w2 * p.x; a1 += w2 * p.y; a2 += w2 * q.x; a3 += w2 * q.y;
            p = __half22float2(*(const __half2*)&u3.x); q = __half22float2(*(const __half2*)&u3.y);
            a0 += w3 * p.x; a1 += w3 * p.y; a2 += w3 * q.x; a3 += w3 * q.y;
        }
    }
    float rd = rsqrtf((float)max(degf, 1));
    float* sa = &sAcc[w * HID];
    sa[4 * lane]     = a0 * rd;
    sa[4 * lane + 1] = a1 * rd;
    sa[4 * lane + 2] = a2 * rd;
    sa[4 * lane + 3] = a3 * rd;
    __syncwarp();

    float o0 = 0.f, o1 = 0.f, o2 = 0.f, o3 = 0.f;
    #pragma unroll 8
    for (int k = 0; k < HID; k++) {
        float av = sa[k];
        const float* wr = &sW[k * HID];
        o0 += av * wr[lane];
        o1 += av * wr[lane + 32];
        o2 += av * wr[lane + 64];
        o3 += av * wr[lane + 96];
    }
    float* out = &g_h2pre[(size_t)v * HID];
    out[lane] = o0; out[lane + 32] = o1; out[lane + 64] = o2; out[lane + 96] = o3;
}

// ---------------- norm / readout --------------------------------------------

// Feature-wise sum & sumsq. grid=1024 x 128 threads, 128 rows per block.
__global__ void k_stats(int layer) {
    int j = threadIdx.x;
    const float* h = (layer == 1) ? g_h1pre : g_h2pre;
    float* stats   = (layer == 1) ? g_stats1 : g_stats2;
    const float* base = &h[(size_t)blockIdx.x * 128 * HID];
    float s = 0.f, ss = 0.f;
    #pragma unroll 8
    for (int r = 0; r < 128; r++) {
        float v = base[r * HID + j];
        s += v;
        ss += v * v;
    }
    atomicAdd(&stats[j], s);
    atomicAdd(&stats[HID + j], ss);
}

// GraphNorm + leaky relu + readout partials. layer1 writes g_h1h (fp16).
__global__ void k_norm(int layer,
                       const float* __restrict__ gamma, const float* __restrict__ beta,
                       const float* __restrict__ alpha) {
    int j = threadIdx.x;
    int b = blockIdx.x;
    const float* stats = (layer == 1) ? g_stats1 : g_stats2;
    const float* hpre  = (layer == 1) ? g_h1pre : g_h2pre;
    int rcol   = (layer == 1) ? 0 : HID;
    int writeH = (layer == 1) ? 1 : 0;

    const float invN = 1.0f / (float)N_NODES;
    float mu  = stats[j] * invN;
    float ex2 = stats[HID + j] * invN;
    float al  = alpha[j];
    float var = ex2 + mu * mu * (al * al - 2.f * al);
    float istd = rsqrtf(var + EPSV);
    float ga = gamma[j] * istd;
    float be = beta[j];
    float amu = al * mu;

    int g = (b * 128) / P_NODES;
    const float* in = &hpre[(size_t)b * 128 * HID];
    __half* out = &g_h1h[(size_t)b * 128 * HID];
    float rsum = 0.f;
    #pragma unroll 4
    for (int r = 0; r < 128; r++) {
        float v = in[r * HID + j];
        float c = (v - amu) * ga + be;
        float y = c > 0.f ? c : SLOPE * c;
        if (writeH) out[r * HID + j] = __float2half(y);
        rsum += y;
    }
    atomicAdd(&g_r[g * (2 * HID) + rcol + j], rsum);
}

__global__ void k_final(const float* __restrict__ Wc, float* __restrict__ out) {
    int t = threadIdx.x;      // 512 threads
    int b = t >> 4, o = t & 15;
    const float* rb = &g_r[b * 2 * HID];
    const float* wr = &Wc[o * 2 * HID];
    float s = 0.f;
    #pragma unroll 8
    for (int k = 0; k < 2 * HID; k++) s += rb[k] * wr[k];
    out[b * OUT_DIM + o] = s * (1.0f / (float)P_NODES);
}

// ---------------- launch -----------------------------------------------------

extern "C" void kernel_launch(void* const* d_in, const int* in_sizes, int n_in,
                              void* d_out, int out_size) {
    const float* features = (const float*)d_in[0];
    const float* ew       = (const float*)d_in[1];
    const int*   src      = (const int*)d_in[2];
    const int*   dst      = (const int*)d_in[3];
    const float* W1       = (const float*)d_in[4];
    const float* W2       = (const float*)d_in[5];
    const float* Wc       = (const float*)d_in[6];
    const float* gamma1   = (const float*)d_in[7];
    const float* beta1    = (const float*)d_in[8];
    const float* alpha1   = (const float*)d_in[9];
    const float* gamma2   = (const float*)d_in[10];
    const float* beta2    = (const float*)d_in[11];
    const float* alpha2   = (const float*)d_in[12];
    float* out = (float*)d_out;

    const int smem2 = (HID * HID + 16 * HID) * (int)sizeof(float);  // 72 KB
    cudaFuncSetAttribute(k_layer2, cudaFuncAttributeMaxDynamicSharedMemorySize, smem2);

    k_zero<<<N_NODES / 256, 256>>>();
    k_build<<<E_EDGES / 256, 256>>>(src, dst, ew);
    k_rs<<<N_NODES / 256, 256>>>();
    k_layer1<<<N_NODES / 16, 512>>>(features, W1);
    k_stats<<<1024, 128>>>(1);
    k_norm<<<1024, 128>>>(1, gamma1, beta1, alpha1);
    k_layer2<<<N_NODES / 16, 512, smem2>>>(W2);
    k_stats<<<1024, 128>>>(2);
    k_norm<<<1024, 128>>>(2, gamma2, beta2, alpha2);
    k_final<<<1, 512>>>(Wc, out);
}

// round 6
// speedup vs baseline: 1.6327x; 1.3578x over previous
#include <cuda_runtime.h>
#include <cuda_fp16.h>

#define N_NODES 131072
#define P_NODES 4096
#define B_GR    32
#define E_EDGES 2097152
#define IN_DIM  64
#define HID     128
#define OUT_DIM 16
#define CAP     64
#define EPSV    1e-5f
#define SLOPE   0.01f

// ---------------- scratch (device globals; no allocations allowed) ----------
__device__ int    g_deg_src[N_NODES];
__device__ int    g_cursor[N_NODES];          // becomes dst degree after build
__device__ float  g_rs_src[N_NODES];
__device__ int    g_csr_src[(size_t)N_NODES * CAP];
__device__ float  g_csr_w[(size_t)N_NODES * CAP];
__device__ float  g_h1pre[(size_t)N_NODES * HID];
__device__ __half g_h1h[(size_t)N_NODES * HID];     // normalized h1 fp16 (gather source)
__device__ float  g_h2pre[(size_t)N_NODES * HID];
__device__ float  g_stats1[2 * HID];
__device__ float  g_stats2[2 * HID];
__device__ float  g_r[B_GR * 2 * HID];

// ---------------- setup -----------------------------------------------------

__global__ void k_zero() {
    int i = blockIdx.x * blockDim.x + threadIdx.x;
    if (i < N_NODES) { g_deg_src[i] = 0; g_cursor[i] = 0; }
    if (i < 2 * HID) { g_stats1[i] = 0.f; g_stats2[i] = 0.f; }
    if (i < B_GR * 2 * HID) { g_r[i] = 0.f; }
}

__global__ void k_build(const int* __restrict__ src, const int* __restrict__ dst,
                        const float* __restrict__ ew) {
    int e = blockIdx.x * blockDim.x + threadIdx.x;
    if (e < E_EDGES) {
        int d = dst[e];
        int s = src[e];
        int pos = atomicAdd(&g_cursor[d], 1);
        atomicAdd(&g_deg_src[s], 1);
        if (pos < CAP) {
            g_csr_src[(size_t)d * CAP + pos] = s;
            g_csr_w[(size_t)d * CAP + pos]   = ew[e];
        }
    }
}

__global__ void k_rs() {
    int v = blockIdx.x * blockDim.x + threadIdx.x;
    if (v < N_NODES) g_rs_src[v] = rsqrtf((float)max(g_deg_src[v], 1));
}

// ---------------- layer 1 ----------------------------------------------------
// 512 threads = 16 warps; each warp gathers 4 nodes, then a 4-node x 4-col
// register-tiled matvec (8 LDS / 16 FMA). Stats fused into epilogue.
__global__ __launch_bounds__(512) void k_layer1(const float* __restrict__ x,
                                                const float* __restrict__ W1) {
    __shared__ float sW[IN_DIM * HID];       // 32 KB
    __shared__ float sBuf[64 * IN_DIM];      // 16 KB: sAcc[64][64], later sRed[2][128][16]
    int tid = threadIdx.x;
    for (int i = tid; i < IN_DIM * HID; i += 512) sW[i] = W1[i];
    __syncthreads();

    int w = tid >> 5, lane = tid & 31;
    int vbase = blockIdx.x * 64 + w * 4;

    // ---- gather 4 nodes ----
    #pragma unroll
    for (int nn = 0; nn < 4; nn++) {
        int v = vbase + nn;
        int degf = g_cursor[v];
        int deg  = min(degf, CAP);
        const int*   cs = &g_csr_src[(size_t)v * CAP];
        const float* cw = &g_csr_w[(size_t)v * CAP];
        float a0 = 0.f, a1 = 0.f;
        for (int base = 0; base < deg; base += 32) {
            int n = min(32, deg - base);
            int s = 0; float wt = 0.f;
            if (lane < n) {
                s  = cs[base + lane];
                wt = cw[base + lane] * g_rs_src[s];
            }
            for (int i = 0; i < n; i += 4) {
                int j1 = min(i + 1, 31), j2 = min(i + 2, 31), j3 = min(i + 3, 31);
                int   s0 = __shfl_sync(0xffffffffu, s,  i);
                int   s1 = __shfl_sync(0xffffffffu, s,  j1);
                int   s2 = __shfl_sync(0xffffffffu, s,  j2);
                int   s3 = __shfl_sync(0xffffffffu, s,  j3);
                float w0 = __shfl_sync(0xffffffffu, wt, i);
                float w1 = __shfl_sync(0xffffffffu, wt, j1);
                float w2 = __shfl_sync(0xffffffffu, wt, j2);
                float w3 = __shfl_sync(0xffffffffu, wt, j3);
                if (i + 1 >= n) w1 = 0.f;
                if (i + 2 >= n) w2 = 0.f;
                if (i + 3 >= n) w3 = 0.f;
                float2 v0 = ((const float2*)&x[(size_t)s0 * IN_DIM])[lane];
                float2 v1 = ((const float2*)&x[(size_t)s1 * IN_DIM])[lane];
                float2 v2 = ((const float2*)&x[(size_t)s2 * IN_DIM])[lane];
                float2 v3 = ((const float2*)&x[(size_t)s3 * IN_DIM])[lane];
                a0 += w0 * v0.x + w1 * v1.x + w2 * v2.x + w3 * v3.x;
                a1 += w0 * v0.y + w1 * v1.y + w2 * v2.y + w3 * v3.y;
            }
        }
        float rd = rsqrtf((float)max(degf, 1));
        float* sa = &sBuf[(w * 4 + nn) * IN_DIM];
        sa[2 * lane]     = a0 * rd;
        sa[2 * lane + 1] = a1 * rd;
    }
    __syncwarp();

    // ---- matvec: 4 nodes x 4 cols per lane ----
    float o[4][4];
    #pragma unroll
    for (int nn = 0; nn < 4; nn++)
        #pragma unroll
        for (int c = 0; c < 4; c++) o[nn][c] = 0.f;

    const float* sa0 = &sBuf[(w * 4 + 0) * IN_DIM];
    const float* sa1 = &sBuf[(w * 4 + 1) * IN_DIM];
    const float* sa2 = &sBuf[(w * 4 + 2) * IN_DIM];
    const float* sa3 = &sBuf[(w * 4 + 3) * IN_DIM];
    #pragma unroll 4
    for (int k = 0; k < IN_DIM; k++) {
        const float* wr = &sW[k * HID + lane];
        float w0 = wr[0], w1 = wr[32], w2 = wr[64], w3 = wr[96];
        float a0 = sa0[k], a1 = sa1[k], a2 = sa2[k], a3 = sa3[k];
        o[0][0] += a0 * w0; o[0][1] += a0 * w1; o[0][2] += a0 * w2; o[0][3] += a0 * w3;
        o[1][0] += a1 * w0; o[1][1] += a1 * w1; o[1][2] += a1 * w2; o[1][3] += a1 * w3;
        o[2][0] += a2 * w0; o[2][1] += a2 * w1; o[2][2] += a2 * w2; o[2][3] += a2 * w3;
        o[3][0] += a3 * w0; o[3][1] += a3 * w1; o[3][2] += a3 * w2; o[3][3] += a3 * w3;
    }
    #pragma unroll
    for (int nn = 0; nn < 4; nn++) {
        float* outp = &g_h1pre[(size_t)(vbase + nn) * HID + lane];
        outp[0] = o[nn][0]; outp[32] = o[nn][1]; outp[64] = o[nn][2]; outp[96] = o[nn][3];
    }

    // ---- fused stats: block partial sum/sumsq per feature ----
    __syncthreads();   // sBuf reuse
    #pragma unroll
    for (int c = 0; c < 4; c++) {
        int j = lane + 32 * c;
        float s  = o[0][c] + o[1][c] + o[2][c] + o[3][c];
        float ss = o[0][c]*o[0][c] + o[1][c]*o[1][c] + o[2][c]*o[2][c] + o[3][c]*o[3][c];
        sBuf[j * 16 + w]        = s;
        sBuf[2048 + j * 16 + w] = ss;
    }
    __syncthreads();
    if (tid < 256) {
        int j = tid & 127;
        int which = tid >> 7;          // 0: sum, 1: sumsq
        const float* p = &sBuf[which * 2048 + j * 16];
        float acc = 0.f;
        #pragma unroll
        for (int i = 0; i < 16; i++) acc += p[i];
        atomicAdd(&g_stats1[which * HID + j], acc);
    }
}

// ---------------- layer 2 ----------------------------------------------------
// dynamic smem: sW 64KB + sAcc 32KB (reused for stats staging) = 96KB.
__global__ __launch_bounds__(512) void k_layer2(const float* __restrict__ W2) {
    extern __shared__ float sm[];
    float* sW   = sm;                  // 128*128
    float* sAcc = sm + HID * HID;      // 64*128
    int tid = threadIdx.x;
    for (int i = tid; i < HID * HID; i += 512) sW[i] = W2[i];
    __syncthreads();

    int w = tid >> 5, lane = tid & 31;
    int vbase = blockIdx.x * 64 + w * 4;

    #pragma unroll
    for (int nn = 0; nn < 4; nn++) {
        int v = vbase + nn;
        int degf = g_cursor[v];
        int deg  = min(degf, CAP);
        const int*   cs = &g_csr_src[(size_t)v * CAP];
        const float* cw = &g_csr_w[(size_t)v * CAP];
        float a0 = 0.f, a1 = 0.f, a2 = 0.f, a3 = 0.f;
        for (int base = 0; base < deg; base += 32) {
            int n = min(32, deg - base);
            int s = 0; float wt = 0.f;
            if (lane < n) {
                s  = cs[base + lane];
                wt = cw[base + lane] * g_rs_src[s];
            }
            for (int i = 0; i < n; i += 4) {
                int j1 = min(i + 1, 31), j2 = min(i + 2, 31), j3 = min(i + 3, 31);
                int   s0 = __shfl_sync(0xffffffffu, s,  i);
                int   s1 = __shfl_sync(0xffffffffu, s,  j1);
                int   s2 = __shfl_sync(0xffffffffu, s,  j2);
                int   s3 = __shfl_sync(0xffffffffu, s,  j3);
                float w0 = __shfl_sync(0xffffffffu, wt, i);
                float w1 = __shfl_sync(0xffffffffu, wt, j1);
                float w2 = __shfl_sync(0xffffffffu, wt, j2);
                float w3 = __shfl_sync(0xffffffffu, wt, j3);
                if (i + 1 >= n) w1 = 0.f;
                if (i + 2 >= n) w2 = 0.f;
                if (i + 3 >= n) w3 = 0.f;
                uint2 u0 = ((const uint2*)&g_h1h[(size_t)s0 * HID])[lane];
                uint2 u1 = ((const uint2*)&g_h1h[(size_t)s1 * HID])[lane];
                uint2 u2 = ((const uint2*)&g_h1h[(size_t)s2 * HID])[lane];
                uint2 u3 = ((const uint2*)&g_h1h[(size_t)s3 * HID])[lane];
                float2 p, q;
                p = __half22float2(*(const __half2*)&u0.x); q = __half22float2(*(const __half2*)&u0.y);
                a0 += w0 * p.x; a1 += w0 * p.y; a2 += w0 * q.x; a3 += w0 * q.y;
                p = __half22float2(*(const __half2*)&u1.x); q = __half22float2(*(const __half2*)&u1.y);
                a0 += w1 * p.x; a1 += w1 * p.y; a2 += w1 * q.x; a3 += w1 * q.y;
                p = __half22float2(*(const __half2*)&u2.x); q = __half22float2(*(const __half2*)&u2.y);
                a0 += w2 * p.x; a1 += w2 * p.y; a2 += w2 * q.x; a3 += w2 * q.y;
                p = __half22float2(*(const __half2*)&u3.x); q = __half22float2(*(const __half2*)&u3.y);
                a0 += w3 * p.x; a1 += w3 * p.y; a2 += w3 * q.x; a3 += w3 * q.y;
            }
        }
        float rd = rsqrtf((float)max(degf, 1));
        float* sa = &sAcc[(w * 4 + nn) * HID];
        sa[4 * lane]     = a0 * rd;
        sa[4 * lane + 1] = a1 * rd;
        sa[4 * lane + 2] = a2 * rd;
        sa[4 * lane + 3] = a3 * rd;
    }
    __syncwarp();

    float o[4][4];
    #pragma unroll
    for (int nn = 0; nn < 4; nn++)
        #pragma unroll
        for (int c = 0; c < 4; c++) o[nn][c] = 0.f;

    const float* sa0 = &sAcc[(w * 4 + 0) * HID];
    const float* sa1 = &sAcc[(w * 4 + 1) * HID];
    const float* sa2 = &sAcc[(w * 4 + 2) * HID];
    const float* sa3 = &sAcc[(w * 4 + 3) * HID];
    #pragma unroll 4
    for (int k = 0; k < HID; k++) {
        const float* wr = &sW[k * HID + lane];
        float w0 = wr[0], w1 = wr[32], w2 = wr[64], w3 = wr[96];
        float a0 = sa0[k], a1 = sa1[k], a2 = sa2[k], a3 = sa3[k];
        o[0][0] += a0 * w0; o[0][1] += a0 * w1; o[0][2] += a0 * w2; o[0][3] += a0 * w3;
        o[1][0] += a1 * w0; o[1][1] += a1 * w1; o[1][2] += a1 * w2; o[1][3] += a1 * w3;
        o[2][0] += a2 * w0; o[2][1] += a2 * w1; o[2][2] += a2 * w2; o[2][3] += a2 * w3;
        o[3][0] += a3 * w0; o[3][1] += a3 * w1; o[3][2] += a3 * w2; o[3][3] += a3 * w3;
    }
    #pragma unroll
    for (int nn = 0; nn < 4; nn++) {
        float* outp = &g_h2pre[(size_t)(vbase + nn) * HID + lane];
        outp[0] = o[nn][0]; outp[32] = o[nn][1]; outp[64] = o[nn][2]; outp[96] = o[nn][3];
    }

    // ---- fused stats ----
    __syncthreads();   // sAcc reuse
    #pragma unroll
    for (int c = 0; c < 4; c++) {
        int j = lane + 32 * c;
        float s  = o[0][c] + o[1][c] + o[2][c] + o[3][c];
        float ss = o[0][c]*o[0][c] + o[1][c]*o[1][c] + o[2][c]*o[2][c] + o[3][c]*o[3][c];
        sAcc[j * 16 + w]        = s;
        sAcc[2048 + j * 16 + w] = ss;
    }
    __syncthreads();
    if (tid < 256) {
        int j = tid & 127;
        int which = tid >> 7;
        const float* p = &sAcc[which * 2048 + j * 16];
        float acc = 0.f;
        #pragma unroll
        for (int i = 0; i < 16; i++) acc += p[i];
        atomicAdd(&g_stats2[which * HID + j], acc);
    }
}

// ---------------- norm / readout --------------------------------------------

__global__ void k_norm(int layer,
                       const float* __restrict__ gamma, const float* __restrict__ beta,
                       const float* __restrict__ alpha) {
    int j = threadIdx.x;
    int b = blockIdx.x;
    const float* stats = (layer == 1) ? g_stats1 : g_stats2;
    const float* hpre  = (layer == 1) ? g_h1pre : g_h2pre;
    int rcol   = (layer == 1) ? 0 : HID;
    int writeH = (layer == 1) ? 1 : 0;

    const float invN = 1.0f / (float)N_NODES;
    float mu  = stats[j] * invN;
    float ex2 = stats[HID + j] * invN;
    float al  = alpha[j];
    float var = ex2 + mu * mu * (al * al - 2.f * al);
    float istd = rsqrtf(var + EPSV);
    float ga = gamma[j] * istd;
    float be = beta[j];
    float amu = al * mu;

    int g = (b * 128) / P_NODES;
    const float* in = &hpre[(size_t)b * 128 * HID];
    __half* out = &g_h1h[(size_t)b * 128 * HID];
    float rsum = 0.f;
    #pragma unroll 4
    for (int r = 0; r < 128; r++) {
        float v = in[r * HID + j];
        float c = (v - amu) * ga + be;
        float y = c > 0.f ? c : SLOPE * c;
        if (writeH) out[r * HID + j] = __float2half(y);
        rsum += y;
    }
    atomicAdd(&g_r[g * (2 * HID) + rcol + j], rsum);
}

__global__ void k_final(const float* __restrict__ Wc, float* __restrict__ out) {
    int t = threadIdx.x;
    int b = t >> 4, o = t & 15;
    const float* rb = &g_r[b * 2 * HID];
    const float* wr = &Wc[o * 2 * HID];
    float s = 0.f;
    #pragma unroll 8
    for (int k = 0; k < 2 * HID; k++) s += rb[k] * wr[k];
    out[b * OUT_DIM + o] = s * (1.0f / (float)P_NODES);
}

// ---------------- launch -----------------------------------------------------

extern "C" void kernel_launch(void* const* d_in, const int* in_sizes, int n_in,
                              void* d_out, int out_size) {
    const float* features = (const float*)d_in[0];
    const float* ew       = (const float*)d_in[1];
    const int*   src      = (const int*)d_in[2];
    const int*   dst      = (const int*)d_in[3];
    const float* W1       = (const float*)d_in[4];
    const float* W2       = (const float*)d_in[5];
    const float* Wc       = (const float*)d_in[6];
    const float* gamma1   = (const float*)d_in[7];
    const float* beta1    = (const float*)d_in[8];
    const float* alpha1   = (const float*)d_in[9];
    const float* gamma2   = (const float*)d_in[10];
    const float* beta2    = (const float*)d_in[11];
    const float* alpha2   = (const float*)d_in[12];
    float* out = (float*)d_out;

    const int smem2 = (HID * HID + 64 * HID) * (int)sizeof(float);  // 96 KB
    cudaFuncSetAttribute(k_layer2, cudaFuncAttributeMaxDynamicSharedMemorySize, smem2);

    k_zero<<<N_NODES / 256, 256>>>();
    k_build<<<E_EDGES / 256, 256>>>(src, dst, ew);
    k_rs<<<N_NODES / 256, 256>>>();
    k_layer1<<<N_NODES / 64, 512>>>(features, W1);
    k_norm<<<1024, 128>>>(1, gamma1, beta1, alpha1);
    k_layer2<<<N_NODES / 64, 512, smem2>>>(W2);
    k_norm<<<1024, 128>>>(2, gamma2, beta2, alpha2);
    k_final<<<1, 512>>>(Wc, out);
}

// round 8
// speedup vs baseline: 2.2260x; 1.3633x over previous
#include <cuda_runtime.h>
#include <cuda_fp16.h>
#include <cuda_bf16.h>
#include <mma.h>
#include <cstdint>

using namespace nvcuda;

#define N_NODES 131072
#define P_NODES 4096
#define B_GR    32
#define E_EDGES 2097152
#define IN_DIM  64
#define HID     128
#define OUT_DIM 16
#define CAP     64
#define EPSV    1e-5f
#define SLOPE   0.01f

// ---------------- scratch (device globals; no allocations allowed) ----------
__device__ int    g_deg_src[N_NODES];
__device__ int    g_cursor[N_NODES];                 // dst degree after build
__device__ float  g_rs_src[N_NODES];
__device__ int    g_csr_src[(size_t)N_NODES * CAP];
__device__ float  g_csr_w[(size_t)N_NODES * CAP];
__device__ int2   g_csre[(size_t)N_NODES * CAP];     // packed {src, w*rs_src}
__device__ __nv_bfloat16 g_agg1[(size_t)N_NODES * IN_DIM];
__device__ __nv_bfloat16 g_agg2[(size_t)N_NODES * HID];
__device__ __nv_bfloat16 g_w1t[HID * IN_DIM];        // W1^T  [n][k]
__device__ __nv_bfloat16 g_w2t[HID * HID];           // W2^T  [n][k]
__device__ float  g_h1pre[(size_t)N_NODES * HID];
__device__ __half g_h1h[(size_t)N_NODES * HID];      // normalized h1 fp16
__device__ float  g_h2pre[(size_t)N_NODES * HID];
__device__ float  g_stats1[2 * HID];
__device__ float  g_stats2[2 * HID];
__device__ float  g_r[B_GR * 2 * HID];

// ---------------- setup -----------------------------------------------------

__global__ void k_zero() {
    int i = blockIdx.x * blockDim.x + threadIdx.x;
    if (i < N_NODES) { g_deg_src[i] = 0; g_cursor[i] = 0; }
    if (i < 2 * HID) { g_stats1[i] = 0.f; g_stats2[i] = 0.f; }
    if (i < B_GR * 2 * HID) { g_r[i] = 0.f; }
}

__global__ void k_build(const int* __restrict__ src, const int* __restrict__ dst,
                        const float* __restrict__ ew) {
    int e = blockIdx.x * blockDim.x + threadIdx.x;
    if (e < E_EDGES) {
        int d = dst[e];
        int s = src[e];
        int pos = atomicAdd(&g_cursor[d], 1);
        atomicAdd(&g_deg_src[s], 1);
        if (pos < CAP) {
            g_csr_src[(size_t)d * CAP + pos] = s;
            g_csr_w[(size_t)d * CAP + pos]   = ew[e];
        }
    }
}

__global__ void k_rs() {
    int v = blockIdx.x * blockDim.x + threadIdx.x;
    if (v < N_NODES) g_rs_src[v] = rsqrtf((float)max(g_deg_src[v], 1));
}

// pack (src, w*rs_src) into int2 per slot; warp per node
__global__ __launch_bounds__(256) void k_fold() {
    int gw = (blockIdx.x * 256 + threadIdx.x) >> 5;
    int lane = threadIdx.x & 31;
    int v = gw;
    int deg = min(g_cursor[v], CAP);
    for (int i = lane; i < deg; i += 32) {
        int s = g_csr_src[(size_t)v * CAP + i];
        float wv = g_csr_w[(size_t)v * CAP + i] * g_rs_src[s];
        g_csre[(size_t)v * CAP + i] = make_int2(s, __float_as_int(wv));
    }
}

// transpose weights to bf16 K-major [n][k]
__global__ void k_prep(const float* __restrict__ W1, const float* __restrict__ W2) {
    int t = threadIdx.x;
    for (int i = t; i < HID * IN_DIM; i += 256) {
        int n = i / IN_DIM, k = i % IN_DIM;
        g_w1t[i] = __float2bfloat16(W1[k * HID + n]);
    }
    for (int i = t; i < HID * HID; i += 256) {
        int n = i / HID, k = i % HID;
        g_w2t[i] = __float2bfloat16(W2[k * HID + n]);
    }
}

// ---------------- aggregation (pure gather) ----------------------------------
// warp per node x4; uniform LDG of packed CSR; lane = 2 features (layer1).
__global__ __launch_bounds__(256) void k_agg1(const float* __restrict__ x) {
    int tid = threadIdx.x, w = tid >> 5, lane = tid & 31;
    int vb = blockIdx.x * 32 + w * 4;
    #pragma unroll
    for (int nn = 0; nn < 4; nn++) {
        int v = vb + nn;
        int degf = g_cursor[v];
        int deg  = min(degf, CAP);
        const int2* ce = &g_csre[(size_t)v * CAP];
        float a0 = 0.f, a1 = 0.f;
        for (int i = 0; i < deg; i += 4) {
            int i1 = min(i + 1, deg - 1), i2 = min(i + 2, deg - 1), i3 = min(i + 3, deg - 1);
            int2 e0 = __ldg(&ce[i]);
            int2 e1 = __ldg(&ce[i1]);
            int2 e2 = __ldg(&ce[i2]);
            int2 e3 = __ldg(&ce[i3]);
            float w0 = __int_as_float(e0.y);
            float w1 = (i + 1 < deg) ? __int_as_float(e1.y) : 0.f;
            float w2 = (i + 2 < deg) ? __int_as_float(e2.y) : 0.f;
            float w3 = (i + 3 < deg) ? __int_as_float(e3.y) : 0.f;
            float2 v0 = ((const float2*)(x + (size_t)e0.x * IN_DIM))[lane];
            float2 v1 = ((const float2*)(x + (size_t)e1.x * IN_DIM))[lane];
            float2 v2 = ((const float2*)(x + (size_t)e2.x * IN_DIM))[lane];
            float2 v3 = ((const float2*)(x + (size_t)e3.x * IN_DIM))[lane];
            a0 += w0 * v0.x + w1 * v1.x + w2 * v2.x + w3 * v3.x;
            a1 += w0 * v0.y + w1 * v1.y + w2 * v2.y + w3 * v3.y;
        }
        float rd = rsqrtf((float)max(degf, 1));
        ((__nv_bfloat162*)&g_agg1[(size_t)v * IN_DIM])[lane] =
            __floats2bfloat162_rn(a0 * rd, a1 * rd);
    }
}

// layer-2 gather from fp16 h1 (lane = 4 features)
__global__ __launch_bounds__(256) void k_agg2() {
    int tid = threadIdx.x, w = tid >> 5, lane = tid & 31;
    int vb = blockIdx.x * 32 + w * 4;
    #pragma unroll
    for (int nn = 0; nn < 4; nn++) {
        int v = vb + nn;
        int degf = g_cursor[v];
        int deg  = min(degf, CAP);
        const int2* ce = &g_csre[(size_t)v * CAP];
        float a0 = 0.f, a1 = 0.f, a2 = 0.f, a3 = 0.f;
        for (int i = 0; i < deg; i += 4) {
            int i1 = min(i + 1, deg - 1), i2 = min(i + 2, deg - 1), i3 = min(i + 3, deg - 1);
            int2 e0 = __ldg(&ce[i]);
            int2 e1 = __ldg(&ce[i1]);
            int2 e2 = __ldg(&ce[i2]);
            int2 e3 = __ldg(&ce[i3]);
            float w0 = __int_as_float(e0.y);
            float w1 = (i + 1 < deg) ? __int_as_float(e1.y) : 0.f;
            float w2 = (i + 2 < deg) ? __int_as_float(e2.y) : 0.f;
            float w3 = (i + 3 < deg) ? __int_as_float(e3.y) : 0.f;
            uint2 u0 = ((const uint2*)(g_h1h + (size_t)e0.x * HID))[lane];
            uint2 u1 = ((const uint2*)(g_h1h + (size_t)e1.x * HID))[lane];
            uint2 u2 = ((const uint2*)(g_h1h + (size_t)e2.x * HID))[lane];
            uint2 u3 = ((const uint2*)(g_h1h + (size_t)e3.x * HID))[lane];
            float2 p, q;
            p = __half22float2(*(const __half2*)&u0.x); q = __half22float2(*(const __half2*)&u0.y);
            a0 += w0 * p.x; a1 += w0 * p.y; a2 += w0 * q.x; a3 += w0 * q.y;
            p = __half22float2(*(const __half2*)&u1.x); q = __half22float2(*(const __half2*)&u1.y);
            a0 += w1 * p.x; a1 += w1 * p.y; a2 += w1 * q.x; a3 += w1 * q.y;
            p = __half22float2(*(const __half2*)&u2.x); q = __half22float2(*(const __half2*)&u2.y);
            a0 += w2 * p.x; a1 += w2 * p.y; a2 += w2 * q.x; a3 += w2 * q.y;
            p = __half22float2(*(const __half2*)&u3.x); q = __half22float2(*(const __half2*)&u3.y);
            a0 += w3 * p.x; a1 += w3 * p.y; a2 += w3 * q.x; a3 += w3 * q.y;
        }
        float rd = rsqrtf((float)max(degf, 1));
        __nv_bfloat162 b0 = __floats2bfloat162_rn(a0 * rd, a1 * rd);
        __nv_bfloat162 b1 = __floats2bfloat162_rn(a2 * rd, a3 * rd);
        uint2 packed;
        packed.x = *(uint32_t*)&b0;
        packed.y = *(uint32_t*)&b1;
        ((uint2*)&g_agg2[(size_t)v * HID])[lane] = packed;
    }
}

// ---------------- WMMA GEMM: agg [M=128,K] @ W^T -> hpre [128,128] -----------
// 256 threads = 8 warps; warp w owns a 16x128 output strip (8 accum frags).
// B fragments read col_major straight from row-major WT[n][k] (ld = pitch).
__global__ __launch_bounds__(256) void k_gemm(int layer) {
    extern __shared__ __nv_bfloat16 smb[];
    const int K   = (layer == 1) ? IN_DIM : HID;
    const int pitch = K + 8;
    __nv_bfloat16* sA = smb;                       // [128][pitch]
    __nv_bfloat16* sB = smb + 128 * pitch;         // [128][pitch]
    const __nv_bfloat16* Ag = (layer == 1) ? g_agg1 : g_agg2;
    const __nv_bfloat16* Bg = (layer == 1) ? g_w1t  : g_w2t;
    int tid = threadIdx.x;
    size_t m0 = (size_t)blockIdx.x * 128;

    int vecs = K / 8;                              // uint4 = 8 bf16
    for (int i = tid; i < 128 * vecs; i += 256) {
        int r = i / vecs, c = i % vecs;
        *(uint4*)&sA[r * pitch + c * 8] = *(const uint4*)&Ag[(m0 + r) * K + c * 8];
        *(uint4*)&sB[r * pitch + c * 8] = *(const uint4*)&Bg[(size_t)r * K + c * 8];
    }
    __syncthreads();

    int w = tid >> 5;
    wmma::fragment<wmma::accumulator, 16, 16, 16, float> acc[8];
    #pragma unroll
    for (int n = 0; n < 8; n++) wmma::fill_fragment(acc[n], 0.f);

    for (int k = 0; k < K; k += 16) {
        wmma::fragment<wmma::matrix_a, 16, 16, 16, __nv_bfloat16, wmma::row_major> fa;
        wmma::load_matrix_sync(fa, &sA[(w * 16) * pitch + k], pitch);
        #pragma unroll
        for (int n = 0; n < 8; n++) {
            wmma::fragment<wmma::matrix_b, 16, 16, 16, __nv_bfloat16, wmma::col_major> fb;
            wmma::load_matrix_sync(fb, &sB[(n * 16) * pitch + k], pitch);
            wmma::mma_sync(acc[n], fa, fb, acc[n]);
        }
    }

    float* H = (layer == 1) ? g_h1pre : g_h2pre;
    #pragma unroll
    for (int n = 0; n < 8; n++)
        wmma::store_matrix_sync(&H[(m0 + w * 16) * HID + n * 16], acc[n], HID,
                                wmma::mem_row_major);
}

// ---------------- stats / norm / readout ------------------------------------

__global__ void k_stats(int layer) {
    int j = threadIdx.x;
    const float* h = (layer == 1) ? g_h1pre : g_h2pre;
    float* st      = (layer == 1) ? g_stats1 : g_stats2;
    const float* base = &h[(size_t)blockIdx.x * 128 * HID];
    float s = 0.f, ss = 0.f;
    #pragma unroll 8
    for (int r = 0; r < 128; r++) {
        float v = base[r * HID + j];
        s += v;
        ss += v * v;
    }
    atomicAdd(&st[j], s);
    atomicAdd(&st[HID + j], ss);
}

__global__ void k_norm(int layer,
                       const float* __restrict__ gamma, const float* __restrict__ beta,
                       const float* __restrict__ alpha) {
    int j = threadIdx.x;
    int b = blockIdx.x;
    const float* stats = (layer == 1) ? g_stats1 : g_stats2;
    const float* hpre  = (layer == 1) ? g_h1pre : g_h2pre;
    int rcol   = (layer == 1) ? 0 : HID;
    int writeH = (layer == 1) ? 1 : 0;

    const float invN = 1.0f / (float)N_NODES;
    float mu  = stats[j] * invN;
    float ex2 = stats[HID + j] * invN;
    float al  = alpha[j];
    float var = ex2 + mu * mu * (al * al - 2.f * al);
    float istd = rsqrtf(var + EPSV);
    float ga = gamma[j] * istd;
    float be = beta[j];
    float amu = al * mu;

    int g = (b * 128) / P_NODES;
    const float* in = &hpre[(size_t)b * 128 * HID];
    __half* out = &g_h1h[(size_t)b * 128 * HID];
    float rsum = 0.f;
    #pragma unroll 4
    for (int r = 0; r < 128; r++) {
        float v = in[r * HID + j];
        float c = (v - amu) * ga + be;
        float y = c > 0.f ? c : SLOPE * c;
        if (writeH) out[r * HID + j] = __float2half(y);
        rsum += y;
    }
    atomicAdd(&g_r[g * (2 * HID) + rcol + j], rsum);
}

__global__ void k_final(const float* __restrict__ Wc, float* __restrict__ out) {
    int t = threadIdx.x;
    int b = t >> 4, o = t & 15;
    const float* rb = &g_r[b * 2 * HID];
    const float* wr = &Wc[o * 2 * HID];
    float s = 0.f;
    #pragma unroll 8
    for (int k = 0; k < 2 * HID; k++) s += rb[k] * wr[k];
    out[b * OUT_DIM + o] = s * (1.0f / (float)P_NODES);
}

// ---------------- launch -----------------------------------------------------

extern "C" void kernel_launch(void* const* d_in, const int* in_sizes, int n_in,
                              void* d_out, int out_size) {
    const float* features = (const float*)d_in[0];
    const float* ew       = (const float*)d_in[1];
    const int*   src      = (const int*)d_in[2];
    const int*   dst      = (const int*)d_in[3];
    const float* W1       = (const float*)d_in[4];
    const float* W2       = (const float*)d_in[5];
    const float* Wc       = (const float*)d_in[6];
    const float* gamma1   = (const float*)d_in[7];
    const float* beta1    = (const float*)d_in[8];
    const float* alpha1   = (const float*)d_in[9];
    const float* gamma2   = (const float*)d_in[10];
    const float* beta2    = (const float*)d_in[11];
    const float* alpha2   = (const float*)d_in[12];
    float* out = (float*)d_out;

    // dynamic smem: 2 tiles of 128 x (K+8) bf16; layer2 worst case K=128
    const int smem1 = 2 * 128 * (IN_DIM + 8) * 2;   // 36864 B
    const int smem2 = 2 * 128 * (HID + 8) * 2;      // 69632 B
    cudaFuncSetAttribute(k_gemm, cudaFuncAttributeMaxDynamicSharedMemorySize, smem2);

    k_zero<<<N_NODES / 256, 256>>>();
    k_build<<<E_EDGES / 256, 256>>>(src, dst, ew);
    k_rs<<<N_NODES / 256, 256>>>();
    k_fold<<<N_NODES / 8, 256>>>();
    k_prep<<<1, 256>>>(W1, W2);

    k_agg1<<<N_NODES / 32, 256>>>(features);
    k_gemm<<<N_NODES / 128, 256, smem1>>>(1);
    k_stats<<<1024, 128>>>(1);
    k_norm<<<1024, 128>>>(1, gamma1, beta1, alpha1);

    k_agg2<<<N_NODES / 32, 256>>>();
    k_gemm<<<N_NODES / 128, 256, smem2>>>(2);
    k_stats<<<1024, 128>>>(2);
    k_norm<<<1024, 128>>>(2, gamma2, beta2, alpha2);

    k_final<<<1, 512>>>(Wc, out);
}